// round 4
// baseline (speedup 1.0000x reference)
#include <cuda_runtime.h>
#include <math.h>
#include <stdint.h>

// ---------------- problem constants ----------------
#define HDIM    2048
#define NE      64           // experts (GEMM N)
#define TM      128          // tokens per CTA (GEMM M)
#define KB      32           // K per chunk
#define NCH     (HDIM/KB)    // 64
#define THREADS 256
#define GAP_TH  2e-3f        // near-tie flag threshold (logit units)
#define FLAG_CAP 8192

// ---------------- dynamic smem layout ----------------
#define XPAD 36
#define XH_OFF 0
#define XL_OFF (128*XPAD*4)
#define WH_OFF (2*128*XPAD*4)
#define WL_OFF (WH_OFF + 64*XPAD*4)
#define BUF_BYTES (WL_OFF + 64*XPAD*4)   // 55296
#define SMEM_TOTAL (2*BUF_BYTES)         // 110592
#define LSP 65

__device__ float g_eload[NE];
__device__ float g_zsum;
__device__ int   g_nflag;
__device__ int   g_flags[FLAG_CAP];

__global__ void zero_kernel() {
    int t = threadIdx.x;
    if (t < NE) g_eload[t] = 0.0f;
    if (t == 0) { g_zsum = 0.0f; g_nflag = 0; }
}

__device__ __forceinline__ float tf32_rn(float v) {
    uint32_t u;
    asm("cvt.rna.tf32.f32 %0, %1;" : "=r"(u) : "f"(v));
    return __uint_as_float(u);
}

__device__ __forceinline__ void mma_tf32(float* d, const float* a, float b0, float b1) {
    asm volatile(
        "mma.sync.aligned.m16n8k8.row.col.f32.tf32.tf32.f32 "
        "{%0,%1,%2,%3}, {%4,%5,%6,%7}, {%8,%9}, {%0,%1,%2,%3};"
        : "+f"(d[0]), "+f"(d[1]), "+f"(d[2]), "+f"(d[3])
        : "r"(__float_as_uint(a[0])), "r"(__float_as_uint(a[1])),
          "r"(__float_as_uint(a[2])), "r"(__float_as_uint(a[3])),
          "r"(__float_as_uint(b0)),  "r"(__float_as_uint(b1)));
}

__global__ __launch_bounds__(THREADS, 1) void gate_kernel(
    const float* __restrict__ x, const float* __restrict__ W,
    float* __restrict__ out, int N)
{
    extern __shared__ __align__(16) char smem[];
    const int tid  = threadIdx.x;
    const int wid  = tid >> 5;
    const int lane = tid & 31;
    const int grp  = lane >> 2;
    const int qid  = lane & 3;
    const int tok0 = blockIdx.x * TM;

    float acc[8][4];
#pragma unroll
    for (int nt = 0; nt < 8; nt++)
#pragma unroll
        for (int i = 0; i < 4; i++) acc[nt][i] = 0.0f;

    float4 px[4], pw[2];
#pragma unroll
    for (int i = 0; i < 4; i++) {
        int s = tid + i * 256; int row = s >> 3; int kq = (s & 7) * 4;
        px[i] = *reinterpret_cast<const float4*>(&x[(size_t)(tok0 + row) * HDIM + kq]);
    }
#pragma unroll
    for (int i = 0; i < 2; i++) {
        int s = tid + i * 256; int e = s >> 3; int kq = (s & 7) * 4;
        pw[i] = *reinterpret_cast<const float4*>(&W[(size_t)e * HDIM + kq]);
    }

    for (int c = 0; c < NCH; c++) {
        const int p = c & 1;
        float* xs_hi = reinterpret_cast<float*>(smem + p * BUF_BYTES + XH_OFF);
        float* xs_lo = reinterpret_cast<float*>(smem + p * BUF_BYTES + XL_OFF);
        float* ws_hi = reinterpret_cast<float*>(smem + p * BUF_BYTES + WH_OFF);
        float* ws_lo = reinterpret_cast<float*>(smem + p * BUF_BYTES + WL_OFF);

        float4 cx[4], cw[2];
#pragma unroll
        for (int i = 0; i < 4; i++) cx[i] = px[i];
#pragma unroll
        for (int i = 0; i < 2; i++) cw[i] = pw[i];

        if (c + 1 < NCH) {
            const int k0 = (c + 1) * KB;
#pragma unroll
            for (int i = 0; i < 4; i++) {
                int s = tid + i * 256; int row = s >> 3; int kq = (s & 7) * 4;
                px[i] = *reinterpret_cast<const float4*>(&x[(size_t)(tok0 + row) * HDIM + k0 + kq]);
            }
#pragma unroll
            for (int i = 0; i < 2; i++) {
                int s = tid + i * 256; int e = s >> 3; int kq = (s & 7) * 4;
                pw[i] = *reinterpret_cast<const float4*>(&W[(size_t)e * HDIM + k0 + kq]);
            }
        }

#pragma unroll
        for (int i = 0; i < 4; i++) {
            int s = tid + i * 256; int row = s >> 3; int kq = (s & 7) * 4;
            float4 v = cx[i], h, l;
            h.x = tf32_rn(v.x); l.x = tf32_rn(v.x - h.x);
            h.y = tf32_rn(v.y); l.y = tf32_rn(v.y - h.y);
            h.z = tf32_rn(v.z); l.z = tf32_rn(v.z - h.z);
            h.w = tf32_rn(v.w); l.w = tf32_rn(v.w - h.w);
            *reinterpret_cast<float4*>(&xs_hi[row * XPAD + kq]) = h;
            *reinterpret_cast<float4*>(&xs_lo[row * XPAD + kq]) = l;
        }
#pragma unroll
        for (int i = 0; i < 2; i++) {
            int s = tid + i * 256; int e = s >> 3; int kq = (s & 7) * 4;
            float4 v = cw[i], h, l;
            h.x = tf32_rn(v.x); l.x = tf32_rn(v.x - h.x);
            h.y = tf32_rn(v.y); l.y = tf32_rn(v.y - h.y);
            h.z = tf32_rn(v.z); l.z = tf32_rn(v.z - h.z);
            h.w = tf32_rn(v.w); l.w = tf32_rn(v.w - h.w);
            *reinterpret_cast<float4*>(&ws_hi[e * XPAD + kq]) = h;
            *reinterpret_cast<float4*>(&ws_lo[e * XPAD + kq]) = l;
        }
        __syncthreads();

        const int r0 = wid * 16 + grp;
        const int r1 = r0 + 8;
#pragma unroll
        for (int ks = 0; ks < 4; ks++) {
            const int k = ks * 8 + qid;
            float aH[4], aL[4];
            aH[0] = xs_hi[r0 * XPAD + k];     aH[1] = xs_hi[r1 * XPAD + k];
            aH[2] = xs_hi[r0 * XPAD + k + 4]; aH[3] = xs_hi[r1 * XPAD + k + 4];
            aL[0] = xs_lo[r0 * XPAD + k];     aL[1] = xs_lo[r1 * XPAD + k];
            aL[2] = xs_lo[r0 * XPAD + k + 4]; aL[3] = xs_lo[r1 * XPAD + k + 4];
#pragma unroll
            for (int nt = 0; nt < 8; nt++) {
                const int n0 = nt * 8 + grp;
                float bH0 = ws_hi[n0 * XPAD + k];
                float bH1 = ws_hi[n0 * XPAD + k + 4];
                float bL0 = ws_lo[n0 * XPAD + k];
                float bL1 = ws_lo[n0 * XPAD + k + 4];
                mma_tf32(acc[nt], aH, bH0, bH1);
                mma_tf32(acc[nt], aH, bL0, bL1);
                mma_tf32(acc[nt], aL, bH0, bH1);
            }
        }
        __syncthreads();
    }

    float* ls = reinterpret_cast<float*>(smem);      // [128][65]
    {
        const int r0 = wid * 16 + grp;
        const int r1 = r0 + 8;
#pragma unroll
        for (int nt = 0; nt < 8; nt++) {
            const int cbase = nt * 8 + qid * 2;
            ls[r0 * LSP + cbase]     = acc[nt][0];
            ls[r0 * LSP + cbase + 1] = acc[nt][1];
            ls[r1 * LSP + cbase]     = acc[nt][2];
            ls[r1 * LSP + cbase + 1] = acc[nt][3];
        }
    }
    __syncthreads();

    if (tid < TM) {
        float lg[NE];
#pragma unroll
        for (int e = 0; e < NE; e++) lg[e] = ls[tid * LSP + e];

        // top-3 scan (ties keep lower index, matches jax top_k)
        float v1 = -1e30f, v2 = -1e30f, v3 = -1e30f;
        int   i1 = 0,      i2 = 0;
#pragma unroll
        for (int e = 0; e < NE; e++) {
            float le = lg[e];
            if (le > v1)      { v3 = v2; v2 = v1; i2 = i1; v1 = le; i1 = e; }
            else if (le > v2) { v3 = v2; v2 = le; i2 = e; }
            else if (le > v3) { v3 = le; }
        }
        const float m = v1;
        float s = 0.0f;
#pragma unroll
        for (int e = 0; e < NE; e++) { lg[e] = expf(lg[e] - m); s += lg[e]; }
        const float inv = 1.0f / s;
#pragma unroll
        for (int e = 0; e < NE; e++) ls[tid * LSP + e] = lg[e] * inv;

        const float p1 = inv;
        const float p2 = expf(v2 - m) * inv;
        const float s1 = 1.0f / (1.0f + expf(p2 - p1));
        const float s2 = 1.0f - s1;

        const int tg = tok0 + tid;
        out[tg * 2 + 0] = s1;
        out[tg * 2 + 1] = s2;
        out[2 * N + tg * 2 + 0] = (float)i1;
        out[2 * N + tg * 2 + 1] = (float)i2;

        // flag near-ties for exact fixup
        if ((v1 - v2 < GAP_TH) || (v2 - v3 < GAP_TH)) {
            int slot = atomicAdd(&g_nflag, 1);
            if (slot < FLAG_CAP) g_flags[slot] = tg;
        }

        float lse = m + logf(s);
        float zz = lse * lse;
#pragma unroll
        for (int o = 16; o > 0; o >>= 1)
            zz += __shfl_xor_sync(0xFFFFFFFFu, zz, o);
        if (lane == 0) atomicAdd(&g_zsum, zz);
    }
    __syncthreads();

    if (tid < NE) {
        float cs = 0.0f;
#pragma unroll 8
        for (int t = 0; t < TM; t++) cs += ls[t * LSP + tid];
        atomicAdd(&g_eload[tid], cs);
    }
}

// ---------------- fp64 fixup for near-tie tokens ----------------
__global__ __launch_bounds__(128) void fixup_kernel(
    const float* __restrict__ x, const float* __restrict__ W,
    float* __restrict__ out, int N)
{
    __shared__ float  xs[HDIM];
    __shared__ double lgs[NE];
    const int tid  = threadIdx.x;
    const int e    = tid & 63;          // expert
    const int half = tid >> 6;          // k-half
    const int nf   = min(g_nflag, FLAG_CAP);

    for (int fi = blockIdx.x; fi < nf; fi += gridDim.x) {
        const int tg = g_flags[fi];
        // stage x row
        for (int k = tid; k < HDIM; k += 128)
            xs[k] = x[(size_t)tg * HDIM + k];
        __syncthreads();

        // fp64 half-dot: thread = (expert, k-half)
        const float* wr = &W[(size_t)e * HDIM + half * (HDIM / 2)];
        const float* xr = &xs[half * (HDIM / 2)];
        double a0 = 0.0, a1 = 0.0, a2 = 0.0, a3 = 0.0;
#pragma unroll 4
        for (int k = 0; k < HDIM / 2; k += 4) {
            a0 += (double)xr[k + 0] * (double)wr[k + 0];
            a1 += (double)xr[k + 1] * (double)wr[k + 1];
            a2 += (double)xr[k + 2] * (double)wr[k + 2];
            a3 += (double)xr[k + 3] * (double)wr[k + 3];
        }
        double d = (a0 + a1) + (a2 + a3);
        if (half == 0) lgs[e] = d;
        __syncthreads();
        if (half == 1) lgs[e] += d;
        __syncthreads();

        if (tid == 0) {
            double v1 = -1e300, v2 = -1e300; int i1 = 0, i2 = 0;
            for (int ee = 0; ee < NE; ee++) {
                double le = lgs[ee];
                if (le > v1)      { v2 = v1; i2 = i1; v1 = le; i1 = ee; }
                else if (le > v2) { v2 = le; i2 = ee; }
            }
            double s = 0.0;
            for (int ee = 0; ee < NE; ee++) s += exp(lgs[ee] - v1);
            double p1 = 1.0 / s;
            double p2 = exp(v2 - v1) / s;
            double e1 = exp(p1 - p1);  // 1.0 (kept for clarity)
            double e2 = exp(p2 - p1);
            float s1 = (float)(e1 / (e1 + e2));
            float s2 = 1.0f - s1;
            out[tg * 2 + 0] = s1;
            out[tg * 2 + 1] = s2;
            out[2 * N + tg * 2 + 0] = (float)i1;
            out[2 * N + tg * 2 + 1] = (float)i2;
        }
        __syncthreads();
    }
}

__global__ void loss_kernel(float* __restrict__ out, int N) {
    __shared__ float sh[NE];
    const int t = threadIdx.x;
    const float invN = 1.0f / (float)N;
    if (t < NE) {
        float d = g_eload[t] * invN - (1.0f / 64.0f);
        sh[t] = d * d;
    }
    __syncthreads();
    if (t == 0) {
        float lb = 0.0f;
#pragma unroll
        for (int e = 0; e < NE; e++) lb += sh[e];
        out[(size_t)4 * N] = 0.01f * lb + 1e-4f * (g_zsum * invN);
    }
}

extern "C" void kernel_launch(void* const* d_in, const int* in_sizes, int n_in,
                              void* d_out, int out_size) {
    const float* x = (const float*)d_in[0];
    const float* W = (const float*)d_in[1];
    float* out = (float*)d_out;
    const int N = in_sizes[0] / HDIM;   // 16384

    cudaFuncSetAttribute(gate_kernel, cudaFuncAttributeMaxDynamicSharedMemorySize, SMEM_TOTAL);
    zero_kernel<<<1, 64>>>();
    gate_kernel<<<N / TM, THREADS, SMEM_TOTAL>>>(x, W, out, N);
    fixup_kernel<<<128, 128>>>(x, W, out, N);
    loss_kernel<<<1, 64>>>(out, N);
}

// round 5
// speedup vs baseline: 5.2402x; 5.2402x over previous
#include <cuda_runtime.h>
#include <cuda_fp16.h>
#include <math.h>
#include <stdint.h>

// ---------------- problem constants ----------------
#define HDIM    2048
#define NE      64           // experts (GEMM N)
#define TM      64           // tokens per CTA (GEMM M)
#define KB      32           // K per chunk (halfs)
#define NCH     (HDIM/KB)    // 64
#define THREADS 128
#define GAP_TH  1e-3f
#define FLAG_CAP 4096

// smem tile: [row][20] u32 (16 half2 data + 4 pad) -> conflict-free frag loads
#define RP 20
#define LSP 65

__device__ float g_eload[NE];
__device__ float g_zsum;
__device__ int   g_nflag;
__device__ int   g_flags[FLAG_CAP];
__device__ float g_flag_lg[FLAG_CAP][NE];

__global__ void zero_kernel() {
    int t = threadIdx.x;
    if (t < NE) g_eload[t] = 0.0f;
    if (t == 0) { g_zsum = 0.0f; g_nflag = 0; }
}

__device__ __forceinline__ void mma_fp16(float* d, const uint32_t* a, uint32_t b0, uint32_t b1) {
    asm volatile(
        "mma.sync.aligned.m16n8k16.row.col.f32.f16.f16.f32 "
        "{%0,%1,%2,%3}, {%4,%5,%6,%7}, {%8,%9}, {%0,%1,%2,%3};"
        : "+f"(d[0]), "+f"(d[1]), "+f"(d[2]), "+f"(d[3])
        : "r"(a[0]), "r"(a[1]), "r"(a[2]), "r"(a[3]), "r"(b0), "r"(b1));
}

__global__ __launch_bounds__(THREADS, 3) void gate_kernel(
    const float* __restrict__ x, const float* __restrict__ W,
    float* __restrict__ out, int N)
{
    __shared__ union {
        uint32_t tiles[2][4][TM * RP];    // [buf][AH,AL,BH,BL][row*RP+h2]
        float    ls[TM][LSP];
    } sm;

    const int tid  = threadIdx.x;
    const int wid  = tid >> 5;
    const int lane = tid & 31;
    const int grp  = lane >> 2;
    const int qid  = lane & 3;
    const int tok0 = blockIdx.x * TM;

    float acc[8][4];
#pragma unroll
    for (int nt = 0; nt < 8; nt++)
#pragma unroll
        for (int i = 0; i < 4; i++) acc[nt][i] = 0.0f;

    // prefetch chunk 0: 4 float4 of x + 4 float4 of W per thread
    float4 px[4], pw[4];
#pragma unroll
    for (int i = 0; i < 4; i++) {
        int s = tid + i * THREADS; int row = s >> 3; int kq = (s & 7) * 4;
        px[i] = *reinterpret_cast<const float4*>(&x[(size_t)(tok0 + row) * HDIM + kq]);
        pw[i] = *reinterpret_cast<const float4*>(&W[(size_t)row * HDIM + kq]);
    }

    for (int c = 0; c < NCH; c++) {
        const int p = c & 1;
        uint32_t* AH = sm.tiles[p][0];
        uint32_t* AL = sm.tiles[p][1];
        uint32_t* BH = sm.tiles[p][2];
        uint32_t* BL = sm.tiles[p][3];

        // convert current prefetch to fp16 hi/lo and store tiles
#pragma unroll
        for (int i = 0; i < 4; i++) {
            int s = tid + i * THREADS; int row = s >> 3; int h2b = (s & 7) * 2;
            {
                float4 v = px[i];
                __half2 h0 = __floats2half2_rn(v.x, v.y);
                __half2 h1 = __floats2half2_rn(v.z, v.w);
                float2 f0 = __half22float2(h0);
                float2 f1 = __half22float2(h1);
                __half2 l0 = __floats2half2_rn(v.x - f0.x, v.y - f0.y);
                __half2 l1 = __floats2half2_rn(v.z - f1.x, v.w - f1.y);
                AH[row * RP + h2b]     = *reinterpret_cast<uint32_t*>(&h0);
                AH[row * RP + h2b + 1] = *reinterpret_cast<uint32_t*>(&h1);
                AL[row * RP + h2b]     = *reinterpret_cast<uint32_t*>(&l0);
                AL[row * RP + h2b + 1] = *reinterpret_cast<uint32_t*>(&l1);
            }
            {
                float4 v = pw[i];
                __half2 h0 = __floats2half2_rn(v.x, v.y);
                __half2 h1 = __floats2half2_rn(v.z, v.w);
                float2 f0 = __half22float2(h0);
                float2 f1 = __half22float2(h1);
                __half2 l0 = __floats2half2_rn(v.x - f0.x, v.y - f0.y);
                __half2 l1 = __floats2half2_rn(v.z - f1.x, v.w - f1.y);
                BH[row * RP + h2b]     = *reinterpret_cast<uint32_t*>(&h0);
                BH[row * RP + h2b + 1] = *reinterpret_cast<uint32_t*>(&h1);
                BL[row * RP + h2b]     = *reinterpret_cast<uint32_t*>(&l0);
                BL[row * RP + h2b + 1] = *reinterpret_cast<uint32_t*>(&l1);
            }
        }

        // issue next-chunk global loads (consumed next iteration)
        if (c + 1 < NCH) {
            const int k0 = (c + 1) * KB;
#pragma unroll
            for (int i = 0; i < 4; i++) {
                int s = tid + i * THREADS; int row = s >> 3; int kq = (s & 7) * 4;
                px[i] = *reinterpret_cast<const float4*>(&x[(size_t)(tok0 + row) * HDIM + k0 + kq]);
                pw[i] = *reinterpret_cast<const float4*>(&W[(size_t)row * HDIM + k0 + kq]);
            }
        }
        __syncthreads();

        // warp = 16 tokens x 64 experts; 2 k16 steps per chunk
        const int r0 = wid * 16 + grp;
        const int r1 = r0 + 8;
#pragma unroll
        for (int ks = 0; ks < 2; ks++) {
            const int h2k = ks * 8 + qid;
            uint32_t aH[4], aL[4];
            aH[0] = AH[r0 * RP + h2k];     aH[1] = AH[r1 * RP + h2k];
            aH[2] = AH[r0 * RP + h2k + 4]; aH[3] = AH[r1 * RP + h2k + 4];
            aL[0] = AL[r0 * RP + h2k];     aL[1] = AL[r1 * RP + h2k];
            aL[2] = AL[r0 * RP + h2k + 4]; aL[3] = AL[r1 * RP + h2k + 4];
#pragma unroll
            for (int nt = 0; nt < 8; nt++) {
                const int n0 = nt * 8 + grp;
                uint32_t bH0 = BH[n0 * RP + h2k];
                uint32_t bH1 = BH[n0 * RP + h2k + 4];
                uint32_t bL0 = BL[n0 * RP + h2k];
                uint32_t bL1 = BL[n0 * RP + h2k + 4];
                mma_fp16(acc[nt], aH, bH0, bH1);
                mma_fp16(acc[nt], aH, bL0, bL1);
                mma_fp16(acc[nt], aL, bH0, bH1);
            }
        }
        // next iter writes the other buffer; sync there protects it
    }
    __syncthreads();

    // ---- stash logits ----
    {
        const int r0 = wid * 16 + grp;
        const int r1 = r0 + 8;
#pragma unroll
        for (int nt = 0; nt < 8; nt++) {
            const int cb = nt * 8 + qid * 2;
            sm.ls[r0][cb]     = acc[nt][0];
            sm.ls[r0][cb + 1] = acc[nt][1];
            sm.ls[r1][cb]     = acc[nt][2];
            sm.ls[r1][cb + 1] = acc[nt][3];
        }
    }
    __syncthreads();

    // ---- per-token epilogue (64 token-threads) ----
    if (tid < TM) {
        float lg[NE];
#pragma unroll
        for (int e = 0; e < NE; e++) lg[e] = sm.ls[tid][e];

        float v1 = -1e30f, v2 = -1e30f, v3 = -1e30f;
        int i1 = 0, i2 = 0;
#pragma unroll
        for (int e = 0; e < NE; e++) {
            float le = lg[e];
            if (le > v1)      { v3 = v2; v2 = v1; i2 = i1; v1 = le; i1 = e; }
            else if (le > v2) { v3 = v2; v2 = le; i2 = e; }
            else if (le > v3) { v3 = le; }
        }
        const int tg = tok0 + tid;

        // near-tie: stash logits for exact fixup
        if ((v1 - v2 < GAP_TH) || (v2 - v3 < GAP_TH)) {
            int slot = atomicAdd(&g_nflag, 1);
            if (slot < FLAG_CAP) {
                g_flags[slot] = tg;
#pragma unroll
                for (int e = 0; e < NE; e++) g_flag_lg[slot][e] = lg[e];
            }
        }

        const float m = v1;
        float s = 0.0f;
#pragma unroll
        for (int e = 0; e < NE; e++) { lg[e] = expf(lg[e] - m); s += lg[e]; }
        const float inv = 1.0f / s;
#pragma unroll
        for (int e = 0; e < NE; e++) sm.ls[tid][e] = lg[e] * inv;

        const float p1 = inv;
        const float p2 = expf(v2 - m) * inv;
        const float s1 = 1.0f / (1.0f + expf(p2 - p1));

        out[tg * 2 + 0] = s1;
        out[tg * 2 + 1] = 1.0f - s1;
        out[2 * N + tg * 2 + 0] = (float)i1;
        out[2 * N + tg * 2 + 1] = (float)i2;

        float lse = m + logf(s);
        float zz = lse * lse;
#pragma unroll
        for (int o = 16; o > 0; o >>= 1)
            zz += __shfl_xor_sync(0xFFFFFFFFu, zz, o);
        if (lane == 0) atomicAdd(&g_zsum, zz);
    }
    __syncthreads();

    if (tid < NE) {
        float cs = 0.0f;
#pragma unroll 8
        for (int t = 0; t < TM; t++) cs += sm.ls[t][tid];
        atomicAdd(&g_eload[tid], cs);
    }
}

// ---------------- candidate-only fp64 fixup ----------------
__global__ __launch_bounds__(128) void fixup_kernel(
    const float* __restrict__ x, const float* __restrict__ W,
    float* __restrict__ out, int N)
{
    __shared__ float  xs[HDIM];
    __shared__ int    cand[16];
    __shared__ int    ncand_sh;
    __shared__ double cval[16];
    __shared__ double wpart[4];
    const int tid = threadIdx.x;
    const int nf  = min(g_nflag, FLAG_CAP);

    for (int fi = blockIdx.x; fi < nf; fi += gridDim.x) {
        const int tg = g_flags[fi];
        const float* lgp = g_flag_lg[fi];

        for (int k = tid; k < HDIM; k += 128)
            xs[k] = x[(size_t)tg * HDIM + k];

        if (tid == 0) {
            float v1 = -1e30f, v2 = -1e30f;
            for (int e = 0; e < NE; e++) {
                float le = lgp[e];
                if (le > v1)      { v2 = v1; v1 = le; }
                else if (le > v2) { v2 = le; }
            }
            float cut = v2 - 2.0f * GAP_TH;
            int nc = 0;
            for (int e = 0; e < NE; e++)
                if (lgp[e] > cut && nc < 16) cand[nc++] = e;
            ncand_sh = nc;
        }
        __syncthreads();
        const int nc = ncand_sh;

        for (int ci = 0; ci < nc; ci++) {
            const float* wr = &W[(size_t)cand[ci] * HDIM];
            double p = 0.0;
            for (int k = tid * 16; k < tid * 16 + 16; k++)
                p += (double)xs[k] * (double)wr[k];
#pragma unroll
            for (int o = 16; o > 0; o >>= 1)
                p += __shfl_xor_sync(0xFFFFFFFFu, p, o);
            if ((tid & 31) == 0) wpart[tid >> 5] = p;
            __syncthreads();
            if (tid == 0) cval[ci] = wpart[0] + wpart[1] + wpart[2] + wpart[3];
            __syncthreads();
        }

        if (tid == 0) {
            double b1 = -1e300, b2 = -1e300; int i1 = 0, i2 = 0;
            for (int ci = 0; ci < nc; ci++) {
                double v = cval[ci]; int e = cand[ci];
                if (v > b1)      { b2 = b1; i2 = i1; b1 = v; i1 = e; }
                else if (v > b2) { b2 = v; i2 = e; }
            }
            // scores from stored fp32 logits (1e-6 accurate)
            float m = lgp[0];
            for (int e = 1; e < NE; e++) m = fmaxf(m, lgp[e]);
            float s = 0.0f;
            for (int e = 0; e < NE; e++) s += expf(lgp[e] - m);
            float inv = 1.0f / s;
            float p1 = expf(lgp[i1] - m) * inv;
            float p2 = expf(lgp[i2] - m) * inv;
            float s1 = 1.0f / (1.0f + expf(p2 - p1));
            out[tg * 2 + 0] = s1;
            out[tg * 2 + 1] = 1.0f - s1;
            out[2 * N + tg * 2 + 0] = (float)i1;
            out[2 * N + tg * 2 + 1] = (float)i2;
        }
        __syncthreads();
    }
}

__global__ void loss_kernel(float* __restrict__ out, int N) {
    __shared__ float sh[NE];
    const int t = threadIdx.x;
    const float invN = 1.0f / (float)N;
    if (t < NE) {
        float d = g_eload[t] * invN - (1.0f / 64.0f);
        sh[t] = d * d;
    }
    __syncthreads();
    if (t == 0) {
        float lb = 0.0f;
#pragma unroll
        for (int e = 0; e < NE; e++) lb += sh[e];
        out[(size_t)4 * N] = 0.01f * lb + 1e-4f * (g_zsum * invN);
    }
}

extern "C" void kernel_launch(void* const* d_in, const int* in_sizes, int n_in,
                              void* d_out, int out_size) {
    const float* x = (const float*)d_in[0];
    const float* W = (const float*)d_in[1];
    float* out = (float*)d_out;
    const int N = in_sizes[0] / HDIM;   // 16384

    zero_kernel<<<1, 64>>>();
    gate_kernel<<<N / TM, THREADS>>>(x, W, out, N);
    fixup_kernel<<<128, 128>>>(x, W, out, N);
    loss_kernel<<<1, 64>>>(out, N);
}